// round 4
// baseline (speedup 1.0000x reference)
#include <cuda_runtime.h>
#include <cuda_bf16.h>
#include <math.h>
#include <stdint.h>

// Problem constants
#define NB 2
#define LT 6400
#define ST 6400
#define CT 256
#define GW 80
#define BORDER 2
#define SQ 0.19764235f   // sqrt(1/(256*0.1))
#define THRESH 0.2f
#define NTIL 50
#define LCH 32
#define LPER (LT / LCH)  // 200
#define SBLK 25
#define INV221 (1.0f / 2097152.0f)  // 1/(64*32768)

// ---------------- scratch ----------------
__device__ float g_sim[(size_t)NB * LT * ST];          // stores E = exp(sim)
__device__ float g_rowinv[NB * LT];
__device__ float g_colinv[NB * ST];
__device__ float g_crowmax[NB * LT];
__device__ float g_ccolmax[NB * ST];
__device__ float g_prs[(size_t)NB * LT * NTIL];
__device__ float g_pcs[(size_t)NB * NTIL * ST];
__device__ float g_pcm[(size_t)NB * LCH * ST];
__device__ float g_crp[(size_t)NB * LT * SBLK];
// operands: bf16 hi + s8 partner/residual
__device__ uint4 g_h0[(size_t)NB * LT * CT / 8];       // bf16 hi A
__device__ uint4 g_h1[(size_t)NB * ST * CT / 8];       // bf16 hi B
__device__ uint32_t g_p0[(size_t)NB * LT * CT / 4];    // s8 partner A (round(64 v))
__device__ uint32_t g_l0[(size_t)NB * LT * CT / 4];    // s8 residual A (round(32768 (v-hi)))
__device__ uint32_t g_p1[(size_t)NB * ST * CT / 4];
__device__ uint32_t g_l1[(size_t)NB * ST * CT / 4];

// ---------------- helpers ----------------
__device__ __forceinline__ uint32_t smem_u32(const void* p) {
    uint32_t a;
    asm("{ .reg .u64 t; cvta.to.shared.u64 t, %1; cvt.u32.u64 %0, t; }" : "=r"(a) : "l"(p));
    return a;
}
__device__ __forceinline__ void cpa16(uint32_t dst, const void* src) {
    asm volatile("cp.async.cg.shared.global [%0], [%1], 16;" :: "r"(dst), "l"(src));
}
#define CP_COMMIT() asm volatile("cp.async.commit_group;")
#define CP_WAIT2()  asm volatile("cp.async.wait_group 2;")
#define CP_WAIT0()  asm volatile("cp.async.wait_group 0;")

__device__ __forceinline__ void ldsm_x4(uint32_t* r, uint32_t addr) {
    asm volatile("ldmatrix.sync.aligned.m8n8.x4.shared.b16 {%0,%1,%2,%3}, [%4];"
        : "=r"(r[0]), "=r"(r[1]), "=r"(r[2]), "=r"(r[3]) : "r"(addr));
}
__device__ __forceinline__ void ldsm_x2(uint32_t* r, uint32_t addr) {
    asm volatile("ldmatrix.sync.aligned.m8n8.x2.shared.b16 {%0,%1}, [%2];"
        : "=r"(r[0]), "=r"(r[1]) : "r"(addr));
}
__device__ __forceinline__ void mma16816(float* d, const uint32_t* a, const uint32_t* b) {
    asm volatile(
        "mma.sync.aligned.m16n8k16.row.col.f32.bf16.bf16.f32 "
        "{%0,%1,%2,%3}, {%4,%5,%6,%7}, {%8,%9}, {%0,%1,%2,%3};"
        : "+f"(d[0]), "+f"(d[1]), "+f"(d[2]), "+f"(d[3])
        : "r"(a[0]), "r"(a[1]), "r"(a[2]), "r"(a[3]), "r"(b[0]), "r"(b[1]));
}
__device__ __forceinline__ void imma16832(int* d, const uint32_t* a, const uint32_t* b) {
    asm volatile(
        "mma.sync.aligned.m16n8k32.row.col.s32.s8.s8.s32 "
        "{%0,%1,%2,%3}, {%4,%5,%6,%7}, {%8,%9}, {%0,%1,%2,%3};"
        : "+r"(d[0]), "+r"(d[1]), "+r"(d[2]), "+r"(d[3])
        : "r"(a[0]), "r"(a[1]), "r"(a[2]), "r"(a[3]), "r"(b[0]), "r"(b[1]));
}

// ---------------- K0: prep (bf16 hi + s8 partner/residual) ----------------
__device__ __forceinline__ uint32_t pack2(float a, float b) {
    __nv_bfloat162 t = __floats2bfloat162_rn(a, b);
    return *(uint32_t*)&t;
}
__device__ __forceinline__ int clamp8(float x) {
    int q = __float2int_rn(x);
    return max(-128, min(127, q));
}
__global__ __launch_bounds__(256) void prep_kernel(const float4* __restrict__ x0,
                                                   const float4* __restrict__ x1) {
    int i = blockIdx.x * 256 + threadIdx.x;  // 4-value groups; covers A then B
    const int half = (size_t)NB * LT * CT / 4;
    float4 v4 = (i < half) ? x0[i] : x1[i - half];
    float v[4] = {v4.x * SQ, v4.y * SQ, v4.z * SQ, v4.w * SQ};
    float h[4];
    uint32_t p8 = 0, l8 = 0;
#pragma unroll
    for (int j = 0; j < 4; j++) {
        __nv_bfloat16 hb = __float2bfloat16(v[j]);
        h[j] = __bfloat162float(hb);
        float al = v[j] - h[j];
        p8 |= ((uint32_t)(clamp8(v[j] * 64.0f) & 0xFF)) << (8 * j);
        l8 |= ((uint32_t)(clamp8(al * 32768.0f) & 0xFF)) << (8 * j);
    }
    uint2 hv = make_uint2(pack2(h[0], h[1]), pack2(h[2], h[3]));
    if (i < half) {
        ((uint2*)g_h0)[i] = hv;
        g_p0[i] = p8;
        g_l0[i] = l8;
    } else {
        int k = i - half;
        ((uint2*)g_h1)[k] = hv;
        g_p1[k] = p8;
        g_l1[k] = l8;
    }
}

// ---------------- K1: hybrid bf16+imma GEMM, E=exp, fused partial sums ----------------
#define KCHUNKS 8             // k32 chunks
#define ABF_B (128 * 80)      // 10240: bf16 tile, 80B rows
#define A8_B (128 * 48)       // 6144:  s8 tile, 48B rows (32B data)
#define STG_B (2 * ABF_B + 4 * A8_B)  // 45056
#define NSTG 3
#define ESTR 132

extern __shared__ char dsm[];

__global__ __launch_bounds__(256, 1) void gemm_mma_kernel() {
    const int n = blockIdx.z;
    const int bm = blockIdx.y * 128;
    const int bn = blockIdx.x * 128;
    const int tid = threadIdx.x;
    const int wid = tid >> 5;
    const int lane = tid & 31;
    const uint32_t sb = smem_u32(dsm);

    const int wm = wid & 3;
    const int wn = wid >> 2;

    float acc[2][8][4];
    int iacc[2][8][4];
#pragma unroll
    for (int mi = 0; mi < 2; mi++)
#pragma unroll
        for (int nj = 0; nj < 8; nj++)
#pragma unroll
            for (int q = 0; q < 4; q++) { acc[mi][nj][q] = 0.0f; iacc[mi][nj][q] = 0; }

    const int lrow = tid >> 1;
    const int half = tid & 1;
    const size_t abase = (size_t)(n * LT + bm + lrow);
    const size_t bbase = (size_t)(n * ST + bn + lrow);

    auto load_chunk = [&](int c, int s) {
        uint32_t st = sb + s * STG_B;
        // bf16 A (64B/row this chunk): 2x16B per thread
        {
            const uint4* src = g_h0 + abase * 32 + c * 4 + half * 2;
            uint32_t d = st + lrow * 80 + half * 32;
            cpa16(d, src);
            cpa16(d + 16, src + 1);
        }
        {
            const uint4* src = g_h1 + bbase * 32 + c * 4 + half * 2;
            uint32_t d = st + ABF_B + lrow * 80 + half * 32;
            cpa16(d, src);
            cpa16(d + 16, src + 1);
        }
        // s8 tiles (32B/row): 1x16B per thread each
        uint32_t d8 = st + 2 * ABF_B + lrow * 48 + half * 16;
        cpa16(d8,               (const uint4*)g_p0 + abase * 16 + c * 2 + half);
        cpa16(d8 + A8_B,        (const uint4*)g_l0 + abase * 16 + c * 2 + half);
        cpa16(d8 + 2 * A8_B,    (const uint4*)g_p1 + bbase * 16 + c * 2 + half);
        cpa16(d8 + 3 * A8_B,    (const uint4*)g_l1 + bbase * 16 + c * 2 + half);
    };

    load_chunk(0, 0); CP_COMMIT();
    load_chunk(1, 1); CP_COMMIT();

    for (int c = 0; c < KCHUNKS; c++) {
        const int s = c % NSTG;
        if (c + 2 < KCHUNKS) {
            load_chunk(c + 2, (c + 2) % NSTG);
            CP_COMMIT();
            CP_WAIT2();
        } else {
            CP_WAIT0();
        }
        __syncthreads();

        const uint32_t Abf = sb + s * STG_B;
        const uint32_t Bbf = Abf + ABF_B;
        const uint32_t Ap = Abf + 2 * ABF_B;
        const uint32_t Al = Ap + A8_B;
        const uint32_t Bp = Al + A8_B;
        const uint32_t Bl = Bp + A8_B;

        const int rA = wm * 32 + ((lane >> 3) & 1) * 8 + (lane & 7);
        const int l16 = lane & 15;
        const int rBo = l16 & 7;

        // ---- bf16 hi·hi phase (2 x k16) ----
#pragma unroll
        for (int kk = 0; kk < 2; kk++) {
            const int kA = kk * 16 + (lane >> 4) * 8;
            const int kB = kk * 16 + ((l16 >> 3) & 1) * 8;
            uint32_t ah[2][4];
#pragma unroll
            for (int mi = 0; mi < 2; mi++)
                ldsm_x4(ah[mi], Abf + (uint32_t)((rA + mi * 16) * 80 + kA * 2));
#pragma unroll
            for (int nj = 0; nj < 8; nj++) {
                uint32_t bh[2];
                ldsm_x2(bh, Bbf + (uint32_t)((wn * 64 + nj * 8 + rBo) * 80 + kB * 2));
#pragma unroll
                for (int mi = 0; mi < 2; mi++) mma16816(acc[mi][nj], ah[mi], bh);
            }
        }

        // ---- imma cross phase (k32) ----
        {
            const uint32_t kA16 = (lane >> 4) * 16;          // byte offset
            const uint32_t kB16 = ((l16 >> 3) & 1) * 16;
            uint32_t ap[2][4], al8[2][4];
#pragma unroll
            for (int mi = 0; mi < 2; mi++) {
                uint32_t ra = (uint32_t)((rA + mi * 16) * 48) + kA16;
                ldsm_x4(ap[mi], Ap + ra);
                ldsm_x4(al8[mi], Al + ra);
            }
#pragma unroll
            for (int nj = 0; nj < 8; nj++) {
                uint32_t rb = (uint32_t)((wn * 64 + nj * 8 + rBo) * 48) + kB16;
                uint32_t bp[2], bl8[2];
                ldsm_x2(bp, Bp + rb);
                ldsm_x2(bl8, Bl + rb);
#pragma unroll
                for (int mi = 0; mi < 2; mi++) {
                    imma16832(iacc[mi][nj], ap[mi], bl8);
                    imma16832(iacc[mi][nj], al8[mi], bp);
                }
            }
        }
        __syncthreads();
    }

    // ---- epilogue: E = exp(sim) -> smem -> store + partial sums ----
    float* et = (float*)dsm;  // 128 x ESTR floats = 67584 B < 135168
#pragma unroll
    for (int mi = 0; mi < 2; mi++) {
        const int r1 = wm * 32 + mi * 16 + (lane >> 2);
#pragma unroll
        for (int nj = 0; nj < 8; nj++) {
            const int cc = wn * 64 + nj * 8 + 2 * (lane & 3);
            float v0 = acc[mi][nj][0] + (float)iacc[mi][nj][0] * INV221;
            float v1 = acc[mi][nj][1] + (float)iacc[mi][nj][1] * INV221;
            float v2 = acc[mi][nj][2] + (float)iacc[mi][nj][2] * INV221;
            float v3 = acc[mi][nj][3] + (float)iacc[mi][nj][3] * INV221;
            et[r1 * ESTR + cc]           = __expf(v0);
            et[r1 * ESTR + cc + 1]       = __expf(v1);
            et[(r1 + 8) * ESTR + cc]     = __expf(v2);
            et[(r1 + 8) * ESTR + cc + 1] = __expf(v3);
        }
    }
    __syncthreads();

    float* Cn = g_sim + (size_t)n * LT * ST;
#pragma unroll
    for (int i = 0; i < 16; i++) {
        int idx = i * 256 + tid;
        int row = idx >> 5;
        int q = idx & 31;
        float4 v = *(float4*)(et + row * ESTR + q * 4);
        *(float4*)(Cn + (size_t)(bm + row) * ST + bn + q * 4) = v;
    }

    {
        int row = tid >> 1, h = tid & 1;
        float s = 0.0f;
        const float* p = et + row * ESTR + h * 64;
#pragma unroll 16
        for (int j = 0; j < 64; j++) s += p[j];
        s += __shfl_xor_sync(0xffffffffu, s, 1);
        if (h == 0) g_prs[(size_t)(n * LT + bm + row) * NTIL + blockIdx.x] = s;
    }
    {
        int col = tid >> 1, h = tid & 1;
        float s = 0.0f;
        const float* p = et + (h * 64) * ESTR + col;
#pragma unroll 16
        for (int j = 0; j < 64; j++) s += p[j * ESTR];
        s += __shfl_xor_sync(0xffffffffu, s, 1);
        if (h == 0) g_pcs[((size_t)n * NTIL + blockIdx.y) * ST + bn + col] = s;
    }
}

// ---------------- merged small reductions ----------------
__global__ __launch_bounds__(256) void sum_merge() {
    int i = blockIdx.x * 256 + threadIdx.x;
    if (i < NB * LT) {
        const float* p = g_prs + (size_t)i * NTIL;
        float s = 0.0f;
#pragma unroll 10
        for (int t = 0; t < NTIL; t++) s += p[t];
        g_rowinv[i] = 1.0f / s;
    } else if (i < NB * LT + NB * ST) {
        int k = i - NB * LT;
        int n = k / ST, s = k % ST;
        float sum = 0.0f;
#pragma unroll 10
        for (int t = 0; t < NTIL; t++) sum += g_pcs[((size_t)n * NTIL + t) * ST + s];
        g_colinv[k] = 1.0f / sum;
    }
}
__global__ __launch_bounds__(256) void max_merge() {
    int i = blockIdx.x * 256 + threadIdx.x;
    if (i < NB * LT) {
        const float* p = g_crp + (size_t)i * SBLK;
        float m = 0.0f;
#pragma unroll
        for (int t = 0; t < SBLK; t++) m = fmaxf(m, p[t]);
        g_crowmax[i] = m;
    } else if (i < NB * LT + NB * ST) {
        int k = i - NB * LT;
        int n = k / ST, s = k % ST;
        float m = 0.0f;
#pragma unroll
        for (int t = 0; t < LCH; t++) m = fmaxf(m, g_pcm[((size_t)(n * LCH + t)) * ST + s]);
        g_ccolmax[k] = m;
    }
}

// ---------------- conf pass ----------------
__global__ __launch_bounds__(256) void conf_kernel(float* __restrict__ out) {
    const int s = blockIdx.x * 256 + threadIdx.x;
    const int by = blockIdx.y, n = blockIdx.z;
    const int lane = threadIdx.x & 31, wid = threadIdx.x >> 5;
    const float ci = g_colinv[n * ST + s];
    __shared__ float wm[8][LPER];

    const size_t base = (size_t)n * LT * ST + (size_t)(by * LPER) * ST + s;
    const float* Eb = g_sim + base;
    float* Ob = out + base;
    float cmax = 0.0f;
    for (int i = 0; i < LPER; i++) {
        const int row = by * LPER + i;
        const float ri = g_rowinv[n * LT + row];
        float E = Eb[(size_t)i * ST];
        float c = E * E * ri * ci;
        Ob[(size_t)i * ST] = c;
        cmax = fmaxf(cmax, c);
        float w = c;
#pragma unroll
        for (int o = 16; o > 0; o >>= 1) w = fmaxf(w, __shfl_xor_sync(0xffffffffu, w, o));
        if (lane == 0) wm[wid][i] = w;
    }
    g_pcm[((size_t)(n * LCH + by)) * ST + s] = cmax;
    __syncthreads();
    for (int i = threadIdx.x; i < LPER; i += 256) {
        float m = wm[0][i];
#pragma unroll
        for (int w = 1; w < 8; w++) m = fmaxf(m, wm[w][i]);
        g_crp[((size_t)n * LT + by * LPER + i) * SBLK + blockIdx.x] = m;
    }
}

// ---------------- finalize ----------------
__global__ __launch_bounds__(256) void finalize_kernel(float* __restrict__ out,
                                                       int write_mask_scores) {
    const unsigned i = (blockIdx.x * 256u + threadIdx.x) * 4u;
    const unsigned s = i % ST;
    const unsigned l = (i / ST) % LT;
    const unsigned n = i / ((unsigned)LT * ST);

    const int h0 = (int)(l / GW), w0 = (int)(l % GW);
    const bool vl = (h0 >= BORDER) && (h0 < GW - BORDER) && (w0 >= BORDER) && (w0 < GW - BORDER);
    const float rm = g_crowmax[n * LT + l];

    const float4 c = *(const float4*)(out + (size_t)i);
    float cv[4] = {c.x, c.y, c.z, c.w};
    float mk[4], sc[4];
    const int h1 = (int)(s / GW);
    const bool vh1 = (h1 >= BORDER) && (h1 < GW - BORDER);
#pragma unroll
    for (int j = 0; j < 4; j++) {
        const int w1 = (int)(s % GW) + j;
        const bool vs = vh1 && (w1 >= BORDER) && (w1 < GW - BORDER);
        const float cc = g_ccolmax[n * ST + s + j];
        const bool ok = (cv[j] > THRESH) && vl && vs && (cv[j] == rm) && (cv[j] == cc);
        mk[j] = ok ? 1.0f : 0.0f;
        sc[j] = ok ? cv[j] : 0.0f;
    }
    if (write_mask_scores) {
        *(float4*)(out + (size_t)NB * LT * ST + i) = make_float4(mk[0], mk[1], mk[2], mk[3]);
        *(float4*)(out + 2 * (size_t)NB * LT * ST + i) = make_float4(sc[0], sc[1], sc[2], sc[3]);
    }
}

// ---------------- host ----------------
extern "C" void kernel_launch(void* const* d_in, const int* in_sizes, int n_in,
                              void* d_out, int out_size) {
    const float* x0 = (const float*)d_in[0];
    const float* x1 = (const float*)d_in[1];
    float* out = (float*)d_out;

    static int smem_set = 0;
    if (!smem_set) {
        cudaFuncSetAttribute(gemm_mma_kernel, cudaFuncAttributeMaxDynamicSharedMemorySize,
                             NSTG * STG_B);
        smem_set = 1;
    }

    prep_kernel<<<(2 * NB * LT * CT / 4) / 256, 256>>>((const float4*)x0, (const float4*)x1);

    gemm_mma_kernel<<<dim3(NTIL, NTIL, NB), 256, NSTG * STG_B>>>();

    sum_merge<<<(NB * (LT + ST) + 255) / 256, 256>>>();

    conf_kernel<<<dim3(SBLK, LCH, NB), 256>>>(out);

    max_merge<<<(NB * (LT + ST) + 255) / 256, 256>>>();

    const size_t tot = (size_t)NB * LT * ST;
    int write_ms = (out_size >= (long long)(3 * tot)) ? 1 : 0;
    finalize_kernel<<<(unsigned)(tot / 4 / 256), 256>>>(out, write_ms);
}

// round 6
// speedup vs baseline: 2.5779x; 2.5779x over previous
#include <cuda_runtime.h>
#include <cuda_bf16.h>
#include <math.h>
#include <stdint.h>

// Problem constants
#define NB 2
#define LT 6400
#define ST 6400
#define CT 256
#define GW 80
#define BORDER 2
#define SQ 0.19764235f   // sqrt(1/(256*0.1)); SQ*SQ == SCALE to ~5e-9
#define THRESH 0.2f
#define NTIL 50          // 6400/128 tiles per dim
#define LCH 32           // l-chunks in conf pass
#define LPER (LT / LCH)  // 200
#define SBLK 7           // s-blocks in conf pass (ceil(6400/1024))

// ---------------- scratch ----------------
__device__ float g_sim[(size_t)NB * LT * ST];          // stores E = exp(sim)
__device__ float g_rowinv[NB * LT];
__device__ float g_colinv[NB * ST];
__device__ float g_crowmax[NB * LT];
__device__ float g_ccolmax[NB * ST];
__device__ float g_prs[(size_t)NB * LT * NTIL];        // row partial sums of E
__device__ float g_pcs[(size_t)NB * NTIL * ST];        // col partial sums of E
__device__ float g_pcm[(size_t)NB * LCH * ST];         // conf col-max partials
__device__ float g_crp[(size_t)NB * LT * SBLK];        // conf row-max partials
// bf16 hi/lo split inputs
__device__ uint4 g_h0[(size_t)NB * LT * CT / 8];
__device__ uint4 g_l0[(size_t)NB * LT * CT / 8];
__device__ uint4 g_h1[(size_t)NB * ST * CT / 8];
__device__ uint4 g_l1[(size_t)NB * ST * CT / 8];

// ---------------- helpers ----------------
__device__ __forceinline__ uint32_t smem_u32(const void* p) {
    uint32_t a;
    asm("{ .reg .u64 t; cvta.to.shared.u64 t, %1; cvt.u32.u64 %0, t; }" : "=r"(a) : "l"(p));
    return a;
}
__device__ __forceinline__ void cpa16(uint32_t dst, const void* src) {
    asm volatile("cp.async.cg.shared.global [%0], [%1], 16;" :: "r"(dst), "l"(src));
}
#define CP_COMMIT() asm volatile("cp.async.commit_group;")
#define CP_WAIT1()  asm volatile("cp.async.wait_group 1;")
#define CP_WAIT0()  asm volatile("cp.async.wait_group 0;")

__device__ __forceinline__ void ldsm_x4(uint32_t* r, uint32_t addr) {
    asm volatile("ldmatrix.sync.aligned.m8n8.x4.shared.b16 {%0,%1,%2,%3}, [%4];"
        : "=r"(r[0]), "=r"(r[1]), "=r"(r[2]), "=r"(r[3]) : "r"(addr));
}
__device__ __forceinline__ void ldsm_x2(uint32_t* r, uint32_t addr) {
    asm volatile("ldmatrix.sync.aligned.m8n8.x2.shared.b16 {%0,%1}, [%2];"
        : "=r"(r[0]), "=r"(r[1]) : "r"(addr));
}
__device__ __forceinline__ void mma16816(float* d, const uint32_t* a, const uint32_t* b) {
    asm volatile(
        "mma.sync.aligned.m16n8k16.row.col.f32.bf16.bf16.f32 "
        "{%0,%1,%2,%3}, {%4,%5,%6,%7}, {%8,%9}, {%0,%1,%2,%3};"
        : "+f"(d[0]), "+f"(d[1]), "+f"(d[2]), "+f"(d[3])
        : "r"(a[0]), "r"(a[1]), "r"(a[2]), "r"(a[3]), "r"(b[0]), "r"(b[1]));
}

// ---------------- K0: fp32 -> scaled bf16 hi/lo split ----------------
__device__ __forceinline__ uint32_t pack2(float a, float b) {
    __nv_bfloat162 t = __floats2bfloat162_rn(a, b);
    return *(uint32_t*)&t;
}
__global__ __launch_bounds__(256) void prep_kernel(const float4* __restrict__ x0,
                                                   const float4* __restrict__ x1) {
    int i = blockIdx.x * 256 + threadIdx.x;
    float4 a = x0[i], b = x1[i];
    float av[4] = {a.x * SQ, a.y * SQ, a.z * SQ, a.w * SQ};
    float bv[4] = {b.x * SQ, b.y * SQ, b.z * SQ, b.w * SQ};
    float ah[4], al[4], bh[4], bl[4];
#pragma unroll
    for (int j = 0; j < 4; j++) {
        __nv_bfloat16 h = __float2bfloat16(av[j]);
        ah[j] = __bfloat162float(h);
        al[j] = av[j] - ah[j];
        h = __float2bfloat16(bv[j]);
        bh[j] = __bfloat162float(h);
        bl[j] = bv[j] - bh[j];
    }
    ((uint2*)g_h0)[i] = make_uint2(pack2(ah[0], ah[1]), pack2(ah[2], ah[3]));
    ((uint2*)g_l0)[i] = make_uint2(pack2(al[0], al[1]), pack2(al[2], al[3]));
    ((uint2*)g_h1)[i] = make_uint2(pack2(bh[0], bh[1]), pack2(bh[2], bh[3]));
    ((uint2*)g_l1)[i] = make_uint2(pack2(bl[0], bl[1]), pack2(bl[2], bl[3]));
}

// ---------------- K1: HMMA GEMM, E=exp(sim), fused row/col partial sums ----------------
#define BK 32
#define KCHUNKS (CT / BK)       // 8
#define ASTR 40                 // bf16 elems per smem row (80B, conflict-free ldmatrix)
#define TILE_B (128 * ASTR * 2) // 10240 bytes per operand tile
#define STG_B (4 * TILE_B)      // 40960 per stage
#define ESTR 132                // epilogue f32 tile stride

extern __shared__ char dsm[];

__global__ __launch_bounds__(256, 2) void gemm_mma_kernel() {
    const int n = blockIdx.z;
    const int bm = blockIdx.y * 128;
    const int bn = blockIdx.x * 128;
    const int tid = threadIdx.x;
    const int wid = tid >> 5;
    const int lane = tid & 31;
    const uint32_t sb = smem_u32(dsm);

    const int wm = wid & 3;   // warp m block (32 rows)
    const int wn = wid >> 2;  // warp n block (64 cols)

    float acc[2][8][4];
#pragma unroll
    for (int mi = 0; mi < 2; mi++)
#pragma unroll
        for (int nj = 0; nj < 8; nj++)
#pragma unroll
            for (int q = 0; q < 4; q++) acc[mi][nj][q] = 0.0f;

    // source rows (uint4 units, row stride = CT/8 = 32)
    const int lrow = tid >> 1;          // 0..127
    const int lq0 = (tid & 1) * 2;      // 0 or 2 (two uint4 each)
    const size_t aoff = (size_t)(n * LT + bm + lrow) * 32;
    const size_t boff = (size_t)(n * ST + bn + lrow) * 32;
    const uint32_t drow = (uint32_t)(lrow * (ASTR * 2));

    // ---- loader: chunk c into stage s ----
    auto load_chunk = [&](int c, int s) {
        uint32_t base = sb + s * STG_B;
        const uint4* pA = g_h0 + aoff + c * 4 + lq0;
        const uint4* pAl = g_l0 + aoff + c * 4 + lq0;
        const uint4* pB = g_h1 + boff + c * 4 + lq0;
        const uint4* pBl = g_l1 + boff + c * 4 + lq0;
#pragma unroll
        for (int q = 0; q < 2; q++) {
            uint32_t d = base + drow + (lq0 + q) * 16;
            cpa16(d, pA + q);
            cpa16(d + TILE_B, pAl + q);
            cpa16(d + 2 * TILE_B, pB + q);
            cpa16(d + 3 * TILE_B, pBl + q);
        }
    };

    load_chunk(0, 0);
    CP_COMMIT();

    for (int c = 0; c < KCHUNKS; c++) {
        const int s = c & 1;
        if (c < KCHUNKS - 1) {
            load_chunk(c + 1, s ^ 1);
            CP_COMMIT();
            CP_WAIT1();
        } else {
            CP_WAIT0();
        }
        __syncthreads();

        const uint32_t AH = sb + s * STG_B;
        const uint32_t AL = AH + TILE_B;
        const uint32_t BH = AH + 2 * TILE_B;
        const uint32_t BL = AH + 3 * TILE_B;

#pragma unroll
        for (int kk = 0; kk < 2; kk++) {
            const int k0 = kk * 16;
            const int rA = wm * 32 + ((lane >> 3) & 1) * 8 + (lane & 7);
            const int kA = k0 + (lane >> 4) * 8;
            uint32_t ah[2][4], al[2][4];
#pragma unroll
            for (int mi = 0; mi < 2; mi++) {
                uint32_t addr = (uint32_t)((rA + mi * 16) * (ASTR * 2) + kA * 2);
                ldsm_x4(ah[mi], AH + addr);
                ldsm_x4(al[mi], AL + addr);
            }
            const int l16 = lane & 15;
            const int rBo = (l16 & 7);
            const int kB = k0 + ((l16 >> 3) & 1) * 8;
#pragma unroll
            for (int nj = 0; nj < 8; nj++) {
                uint32_t addr = (uint32_t)((wn * 64 + nj * 8 + rBo) * (ASTR * 2) + kB * 2);
                uint32_t bh[2], bl[2];
                ldsm_x2(bh, BH + addr);
                ldsm_x2(bl, BL + addr);
#pragma unroll
                for (int mi = 0; mi < 2; mi++) {
                    mma16816(acc[mi][nj], ah[mi], bh);
                    mma16816(acc[mi][nj], ah[mi], bl);
                    mma16816(acc[mi][nj], al[mi], bh);
                }
            }
        }
        __syncthreads();
    }

    // ---- epilogue: E = exp(acc) -> smem tile -> store + partial sums ----
    float* et = (float*)dsm;  // 128 x ESTR floats (67584 B < 81920)
#pragma unroll
    for (int mi = 0; mi < 2; mi++) {
        const int r1 = wm * 32 + mi * 16 + (lane >> 2);
#pragma unroll
        for (int nj = 0; nj < 8; nj++) {
            const int cc = wn * 64 + nj * 8 + 2 * (lane & 3);
            et[r1 * ESTR + cc]           = __expf(acc[mi][nj][0]);
            et[r1 * ESTR + cc + 1]       = __expf(acc[mi][nj][1]);
            et[(r1 + 8) * ESTR + cc]     = __expf(acc[mi][nj][2]);
            et[(r1 + 8) * ESTR + cc + 1] = __expf(acc[mi][nj][3]);
        }
    }
    __syncthreads();

    // coalesced store of E tile
    float* Cn = g_sim + (size_t)n * LT * ST;
#pragma unroll
    for (int i = 0; i < 16; i++) {
        int idx = i * 256 + tid;
        int row = idx >> 5;
        int q = idx & 31;
        float4 v = *(float4*)(et + row * ESTR + q * 4);
        *(float4*)(Cn + (size_t)(bm + row) * ST + bn + q * 4) = v;
    }

    // row partial sums: 2 threads per row
    {
        int row = tid >> 1, h = tid & 1;
        float s = 0.0f;
        const float* p = et + row * ESTR + h * 64;
#pragma unroll 16
        for (int j = 0; j < 64; j++) s += p[j];
        s += __shfl_xor_sync(0xffffffffu, s, 1);
        if (h == 0) g_prs[(size_t)(n * LT + bm + row) * NTIL + blockIdx.x] = s;
    }
    // col partial sums: 2 threads per col
    {
        int col = tid >> 1, h = tid & 1;
        float s = 0.0f;
        const float* p = et + (h * 64) * ESTR + col;
#pragma unroll 16
        for (int j = 0; j < 64; j++) s += p[j * ESTR];
        s += __shfl_xor_sync(0xffffffffu, s, 1);
        if (h == 0) g_pcs[((size_t)n * NTIL + blockIdx.y) * ST + bn + col] = s;
    }
}

// ---------------- merged small reductions ----------------
__global__ __launch_bounds__(256) void sum_merge() {
    int i = blockIdx.x * 256 + threadIdx.x;
    if (i < NB * LT) {
        const float* p = g_prs + (size_t)i * NTIL;
        float s = 0.0f;
#pragma unroll 10
        for (int t = 0; t < NTIL; t++) s += p[t];
        g_rowinv[i] = 1.0f / s;
    } else if (i < NB * LT + NB * ST) {
        int k = i - NB * LT;
        int n = k / ST, s = k % ST;
        float sum = 0.0f;
#pragma unroll 10
        for (int t = 0; t < NTIL; t++) sum += g_pcs[((size_t)n * NTIL + t) * ST + s];
        g_colinv[k] = 1.0f / sum;
    }
}
__global__ __launch_bounds__(256) void max_merge() {
    int i = blockIdx.x * 256 + threadIdx.x;
    if (i < NB * LT) {
        const float* p = g_crp + (size_t)i * SBLK;
        float m = 0.0f;
#pragma unroll
        for (int t = 0; t < SBLK; t++) m = fmaxf(m, p[t]);
        g_crowmax[i] = m;
    } else if (i < NB * LT + NB * ST) {
        int k = i - NB * LT;
        int n = k / ST, s = k % ST;
        float m = 0.0f;
#pragma unroll
        for (int t = 0; t < LCH; t++) m = fmaxf(m, g_pcm[((size_t)(n * LCH + t)) * ST + s]);
        g_ccolmax[k] = m;
    }
}

// ---------------- conf pass: thread owns 4 cols (float4), walks 200 rows ----------------
// grid: (SBLK=7, LCH=32, NB); block 256. Block covers 1024 columns.
__global__ __launch_bounds__(256) void conf_kernel(float* __restrict__ out) {
    const int s0 = blockIdx.x * 1024 + threadIdx.x * 4;
    const int by = blockIdx.y, n = blockIdx.z;
    const int lane = threadIdx.x & 31, wid = threadIdx.x >> 5;
    const bool valid = (s0 < ST);

    __shared__ float ris[LPER];
    __shared__ float wm[8][LPER];
    for (int i = threadIdx.x; i < LPER; i += 256)
        ris[i] = g_rowinv[n * LT + by * LPER + i];
    __syncthreads();

    float4 ci = valid ? *(const float4*)(g_colinv + n * ST + s0)
                      : make_float4(0.f, 0.f, 0.f, 0.f);

    const size_t base = (size_t)n * LT * ST + (size_t)(by * LPER) * ST + s0;
    const float* Eb = g_sim + base;
    float* Ob = out + base;

    float cm0 = 0.f, cm1 = 0.f, cm2 = 0.f, cm3 = 0.f;
    for (int i = 0; i < LPER; i++) {
        const float ri = ris[i];
        float4 c = make_float4(0.f, 0.f, 0.f, 0.f);
        if (valid) {
            float4 E = *(const float4*)(Eb + (size_t)i * ST);
            c.x = E.x * E.x * ri * ci.x;
            c.y = E.y * E.y * ri * ci.y;
            c.z = E.z * E.z * ri * ci.z;
            c.w = E.w * E.w * ri * ci.w;
            *(float4*)(Ob + (size_t)i * ST) = c;
            cm0 = fmaxf(cm0, c.x); cm1 = fmaxf(cm1, c.y);
            cm2 = fmaxf(cm2, c.z); cm3 = fmaxf(cm3, c.w);
        }
        float w = fmaxf(fmaxf(c.x, c.y), fmaxf(c.z, c.w));
#pragma unroll
        for (int o = 16; o > 0; o >>= 1) w = fmaxf(w, __shfl_xor_sync(0xffffffffu, w, o));
        if (lane == 0) wm[wid][i] = w;
    }
    if (valid)
        *(float4*)(g_pcm + ((size_t)(n * LCH + by)) * ST + s0) = make_float4(cm0, cm1, cm2, cm3);
    __syncthreads();
    for (int i = threadIdx.x; i < LPER; i += 256) {
        float m = wm[0][i];
#pragma unroll
        for (int w = 1; w < 8; w++) m = fmaxf(m, wm[w][i]);
        g_crp[((size_t)n * LT + by * LPER + i) * SBLK + blockIdx.x] = m;
    }
}

// ---------------- finalize: mask + scores ----------------
__global__ __launch_bounds__(256) void finalize_kernel(float* __restrict__ out,
                                                       int write_mask_scores) {
    const unsigned i = (blockIdx.x * 256u + threadIdx.x) * 4u;
    const unsigned s = i % ST;
    const unsigned l = (i / ST) % LT;
    const unsigned n = i / ((unsigned)LT * ST);

    const int h0 = (int)(l / GW), w0 = (int)(l % GW);
    const bool vl = (h0 >= BORDER) && (h0 < GW - BORDER) && (w0 >= BORDER) && (w0 < GW - BORDER);
    const float rm = g_crowmax[n * LT + l];

    const float4 c = *(const float4*)(out + (size_t)i);
    float cv[4] = {c.x, c.y, c.z, c.w};
    float mk[4], sc[4];
    const int h1 = (int)(s / GW);
    const bool vh1 = (h1 >= BORDER) && (h1 < GW - BORDER);
#pragma unroll
    for (int j = 0; j < 4; j++) {
        const int w1 = (int)(s % GW) + j;
        const bool vs = vh1 && (w1 >= BORDER) && (w1 < GW - BORDER);
        const float cc = g_ccolmax[n * ST + s + j];
        const bool ok = (cv[j] > THRESH) && vl && vs && (cv[j] == rm) && (cv[j] == cc);
        mk[j] = ok ? 1.0f : 0.0f;
        sc[j] = ok ? cv[j] : 0.0f;
    }
    if (write_mask_scores) {
        *(float4*)(out + (size_t)NB * LT * ST + i) = make_float4(mk[0], mk[1], mk[2], mk[3]);
        *(float4*)(out + 2 * (size_t)NB * LT * ST + i) = make_float4(sc[0], sc[1], sc[2], sc[3]);
    }
}

// ---------------- host ----------------
extern "C" void kernel_launch(void* const* d_in, const int* in_sizes, int n_in,
                              void* d_out, int out_size) {
    const float* x0 = (const float*)d_in[0];
    const float* x1 = (const float*)d_in[1];
    float* out = (float*)d_out;

    static int smem_set = 0;
    if (!smem_set) {
        cudaFuncSetAttribute(gemm_mma_kernel, cudaFuncAttributeMaxDynamicSharedMemorySize,
                             2 * STG_B);
        smem_set = 1;
    }

    prep_kernel<<<(NB * LT * CT / 4) / 256, 256>>>((const float4*)x0, (const float4*)x1);

    gemm_mma_kernel<<<dim3(NTIL, NTIL, NB), 256, 2 * STG_B>>>();

    sum_merge<<<(NB * (LT + ST) + 255) / 256, 256>>>();

    conf_kernel<<<dim3(SBLK, LCH, NB), 256>>>(out);

    max_merge<<<(NB * (LT + ST) + 255) / 256, 256>>>();

    const size_t tot = (size_t)NB * LT * ST;
    int write_ms = (out_size >= (long long)(3 * tot)) ? 1 : 0;
    finalize_kernel<<<(unsigned)(tot / 4 / 256), 256>>>(out, write_ms);
}